// round 1
// baseline (speedup 1.0000x reference)
#include <cuda_runtime.h>

// Problem constants
#define BB    16
#define SS    400
#define DD    768
#define HH    512
#define OUTD  256
#define SKPD  192
#define EE    8
#define NPAIR 32         // B * K, exactly 2 experts per batch
#define H4    2048       // 4*H
#define YELEMS (BB*SS*OUTD)
#define NB_REC 128       // persistent recurrence blocks (must all be co-resident)

// ---------------- device scratch (static, no allocs) ----------------
__device__ float d_WT[EE*HH*H4];             // W_hh transposed: [e][j][k]   33.5 MB
__device__ float d_xp[NPAIR*SS*H4];          // input projections per pair  104.8 MB
__device__ float d_hsw[NPAIR*SS*HH];         // gate-weighted h sequence     26.2 MB
__device__ float d_hbuf[2*NPAIR*HH];         // double-buffered h state
__device__ int   d_pair_e[NPAIR];
__device__ float d_pair_g[NPAIR];
__device__ int   d_epairs[EE*16];            // pair indices per expert
__device__ int   d_ecnt[EE];
__device__ unsigned d_bar;

// ============================================================
// Kernel 1: gating + loss + bookkeeping + state init
// ============================================================
__global__ void __launch_bounds__(256) gate_kernel(
    const float* __restrict__ spk, const float* __restrict__ Wg,
    const float* __restrict__ bg, float* __restrict__ out, int out_size)
{
    __shared__ float lg[BB][EE];
    __shared__ float gm[BB][EE];
    int tid = threadIdx.x;

    if (tid < BB*EE) {
        int b = tid >> 3, e = tid & 7;
        float s = bg[e];
        for (int k = 0; k < SKPD; ++k) s += spk[b*SKPD + k] * Wg[e*SKPD + k];
        lg[b][e] = s;
        gm[b][e] = 0.f;
    }
    __syncthreads();

    if (tid < BB) {
        int b = tid;
        // top-1 (first index wins ties, matches lax.top_k stability)
        int i0 = 0; float m0 = lg[b][0];
        for (int e = 1; e < EE; ++e) if (lg[b][e] > m0) { m0 = lg[b][e]; i0 = e; }
        // top-2
        int i1 = -1; float m1 = -1e30f;
        for (int e = 0; e < EE; ++e) if (e != i0 && lg[b][e] > m1) { m1 = lg[b][e]; i1 = e; }
        // softmax over the two top logits
        float e1v = __expf(m1 - m0);
        float den = 1.f + e1v;
        float g0 = 1.f / den, g1 = e1v / den;
        d_pair_e[2*b]   = i0;  d_pair_e[2*b+1] = i1;
        d_pair_g[2*b]   = g0;  d_pair_g[2*b+1] = g1;
        gm[b][i0] = g0; gm[b][i1] = g1;
    }
    __syncthreads();

    if (tid == 0) {
        int cnt[EE];
        for (int e = 0; e < EE; ++e) cnt[e] = 0;
        for (int p = 0; p < NPAIR; ++p) {
            int e = d_pair_e[p];
            d_epairs[e*16 + cnt[e]] = p;
            cnt[e]++;
        }
        for (int e = 0; e < EE; ++e) d_ecnt[e] = cnt[e];

        // loss = (cv2(importance) + cv2(load)) * 0.01
        float imp[EE], ldv[EE];
        for (int e = 0; e < EE; ++e) { imp[e] = 0.f; ldv[e] = (float)cnt[e]; }
        for (int b = 0; b < BB; ++b)
            for (int e = 0; e < EE; ++e) imp[e] += gm[b][e];

        float loss = 0.f;
        for (int which = 0; which < 2; ++which) {
            const float* v = which ? ldv : imp;
            float mean = 0.f;
            for (int e = 0; e < EE; ++e) mean += v[e];
            mean /= (float)EE;
            float var = 0.f;
            for (int e = 0; e < EE; ++e) { float d = v[e]-mean; var += d*d; }
            var /= (float)(EE - 1);               // ddof=1
            loss += var / (mean*mean + 1e-10f);
        }
        loss *= 0.01f;
        for (int i = YELEMS; i < out_size; ++i) out[i] = loss;

        d_bar = 0u;                               // reset grid barrier
    }

    // zero both h buffers
    for (int i = tid; i < 2*NPAIR*HH; i += blockDim.x) d_hbuf[i] = 0.f;
}

// ============================================================
// Kernel 2: transpose W_hh -> WT[e][j][k]
// ============================================================
__global__ void transpose_kernel(const float* __restrict__ W_hh)
{
    __shared__ float t[32][33];
    int e  = blockIdx.z;
    int kt = blockIdx.y;   // 0..63   (rows k of W_hh, 2048/32)
    int jt = blockIdx.x;   // 0..15   (cols j, 512/32)
    int x = threadIdx.x, y = threadIdx.y;   // 32 x 8
    const float* src = W_hh + (size_t)e*H4*HH;
    float* dst = d_WT + (size_t)e*HH*H4;
    #pragma unroll
    for (int i = 0; i < 32; i += 8)
        t[y+i][x] = src[(size_t)(kt*32 + y+i)*HH + jt*32 + x];
    __syncthreads();
    #pragma unroll
    for (int i = 0; i < 32; i += 8)
        dst[(size_t)(jt*32 + y+i)*H4 + kt*32 + x] = t[x][y+i];
}

// ============================================================
// Kernel 3: xp[p][s][k] = x[b_p] @ W_ih[e_p]^T + b_ih + b_hh
//           128x128x8 register-tiled SGEMM, NT form
// ============================================================
__global__ void __launch_bounds__(256) xp_kernel(
    const float* __restrict__ x, const float* __restrict__ W_ih,
    const float* __restrict__ b_ih, const float* __restrict__ b_hh)
{
    const int p = blockIdx.z;
    const int e = d_pair_e[p];
    const int b = p >> 1;
    const float* A  = x    + (size_t)b*SS*DD;      // [400,768]
    const float* Bw = W_ih + (size_t)e*H4*DD;      // [2048,768]

    __shared__ float As[8][132];
    __shared__ float Bs[8][132];

    const int tid = threadIdx.x;
    const int tx = tid & 15, ty = tid >> 4;        // 16x16 thread tile
    const int lrow = tid >> 1, lcg = (tid & 1) * 4;
    const int m0 = blockIdx.y * 128, k0 = blockIdx.x * 128;

    float acc[8][8];
    #pragma unroll
    for (int i = 0; i < 8; ++i)
        #pragma unroll
        for (int j = 0; j < 8; ++j) acc[i][j] = 0.f;

    for (int d0 = 0; d0 < DD; d0 += 8) {
        int gm = m0 + lrow;
        float4 av = (gm < SS) ? *(const float4*)(A + (size_t)gm*DD + d0 + lcg)
                              : make_float4(0.f,0.f,0.f,0.f);
        float4 bv = *(const float4*)(Bw + (size_t)(k0 + lrow)*DD + d0 + lcg);
        __syncthreads();
        As[lcg+0][lrow]=av.x; As[lcg+1][lrow]=av.y; As[lcg+2][lrow]=av.z; As[lcg+3][lrow]=av.w;
        Bs[lcg+0][lrow]=bv.x; Bs[lcg+1][lrow]=bv.y; Bs[lcg+2][lrow]=bv.z; Bs[lcg+3][lrow]=bv.w;
        __syncthreads();
        #pragma unroll
        for (int kk = 0; kk < 8; ++kk) {
            float4 a0 = *(const float4*)&As[kk][ty*8];
            float4 a1 = *(const float4*)&As[kk][ty*8+4];
            float4 b0 = *(const float4*)&Bs[kk][tx*8];
            float4 b1 = *(const float4*)&Bs[kk][tx*8+4];
            float ra[8] = {a0.x,a0.y,a0.z,a0.w,a1.x,a1.y,a1.z,a1.w};
            float rb[8] = {b0.x,b0.y,b0.z,b0.w,b1.x,b1.y,b1.z,b1.w};
            #pragma unroll
            for (int i = 0; i < 8; ++i)
                #pragma unroll
                for (int j = 0; j < 8; ++j)
                    acc[i][j] = fmaf(ra[i], rb[j], acc[i][j]);
        }
    }

    #pragma unroll
    for (int i = 0; i < 8; ++i) {
        int gm = m0 + ty*8 + i;
        if (gm >= SS) continue;
        float* orow = d_xp + ((size_t)p*SS + gm)*H4 + k0 + tx*8;
        #pragma unroll
        for (int j = 0; j < 8; ++j) {
            int k = k0 + tx*8 + j;
            orow[j] = acc[i][j] + __ldg(b_ih + e*H4 + k) + __ldg(b_hh + e*H4 + k);
        }
    }
}

// ============================================================
// Kernel 4: persistent LSTM recurrence, one grid barrier / step
// ============================================================
__device__ __forceinline__ void grid_bar(unsigned* target)
{
    __threadfence();
    __syncthreads();
    if (threadIdx.x == 0) {
        atomicAdd(&d_bar, 1u);
        *target += NB_REC;
        while (*((volatile unsigned*)&d_bar) < *target) { }
    }
    __syncthreads();
}

template<int NP>
__device__ void rec_loop(float* hsm, float* gsm, int np, int e, int u0)
{
    const int tid  = threadIdx.x;
    const int w    = tid >> 5, lane = tid & 31;
    const int gate = w >> 1,  half = w & 1;      // warps 0..7 -> (gate, j-half)

    int plist[NP];
    #pragma unroll
    for (int i = 0; i < NP; ++i)
        plist[i] = d_epairs[e*16 + ((i < np) ? i : 0)];   // pad with pair 0

    // column pointer into WT: element [j][gate*H + u0 + lane], stride H4 per j
    const float* WTcol = d_WT + (size_t)e*HH*H4 + gate*HH + u0 + lane
                              + (size_t)(half*256)*H4;

    float c0 = 0.f, c1 = 0.f;
    unsigned target = 0;

    for (int s = 0; s < SS; ++s) {
        const float* hbuf = d_hbuf + (s & 1) * NPAIR*HH;
        float*       hnxt = d_hbuf + ((s+1) & 1) * NPAIR*HH;

        // load h_prev of (padded) pairs into smem, L2-coherent loads
        const int npp = (np < NP) ? NP : np;     // == NP
        for (int idx = tid; idx < npp*HH; idx += 256) {
            int p = idx >> 9, j = idx & (HH-1);
            hsm[idx] = __ldcg(hbuf + plist[p]*HH + j);
        }
        __syncthreads();

        // GEMV: each lane owns one W-row; j broadcast from smem -> no reductions
        float acc[NP];
        #pragma unroll
        for (int p = 0; p < NP; ++p) acc[p] = 0.f;
        const int jb = half * 256;
        for (int j = 0; j < 256; j += 4) {
            float w0 = WTcol[(size_t)(j+0)*H4];
            float w1 = WTcol[(size_t)(j+1)*H4];
            float w2 = WTcol[(size_t)(j+2)*H4];
            float w3 = WTcol[(size_t)(j+3)*H4];
            #pragma unroll
            for (int p = 0; p < NP; ++p) {
                float4 h4 = *(const float4*)&hsm[p*HH + jb + j];
                acc[p] = fmaf(w3, h4.w, fmaf(w2, h4.z,
                         fmaf(w1, h4.y, fmaf(w0, h4.x, acc[p]))));
            }
        }

        // two-stage combine of the two j-halves into gsm[p][gate][lane]
        if (half == 0) {
            #pragma unroll
            for (int p = 0; p < NP; ++p) gsm[(p*4 + gate)*32 + lane] = acc[p];
        }
        __syncthreads();
        if (half == 1) {
            #pragma unroll
            for (int p = 0; p < NP; ++p) gsm[(p*4 + gate)*32 + lane] += acc[p];
        }
        __syncthreads();

        // activation: covers np*32 (p,u) slots; c state in registers
        const int na = np * 32;
        #pragma unroll
        for (int rep = 0; rep < 2; ++rep) {
            int idx = tid + rep*256;
            if (idx < na) {
                int p = idx >> 5, u = idx & 31;
                int pr = (p < NP) ? plist[p] : 0;
                const float* xprow = d_xp + ((size_t)pr*SS + s)*H4 + u0 + u;
                float gi = gsm[(p*4+0)*32+u] + xprow[0];
                float gf = gsm[(p*4+1)*32+u] + xprow[512];
                float gg = gsm[(p*4+2)*32+u] + xprow[1024];
                float go = gsm[(p*4+3)*32+u] + xprow[1536];
                float iv = 1.f / (1.f + __expf(-gi));
                float fv = 1.f / (1.f + __expf(-gf));
                float cp = rep ? c1 : c0;
                float cn = fv * cp + iv * tanhf(gg);
                float hv = (1.f / (1.f + __expf(-go))) * tanhf(cn);
                if (rep) c1 = cn; else c0 = cn;
                hnxt[pr*HH + u0 + u] = hv;
                d_hsw[((size_t)pr*SS + s)*HH + u0 + u] = d_pair_g[pr] * hv;
            }
        }

        grid_bar(&target);
    }
}

__global__ void __launch_bounds__(256) rec_kernel()
{
    __shared__ float hsm[16*HH];       // 32 KB
    __shared__ float gsm[16*4*32];     //  8 KB
    const int e  = blockIdx.x >> 4;
    const int uc = blockIdx.x & 15;
    const int u0 = uc * 32;
    const int np = d_ecnt[e];

    if (np == 0) {
        unsigned target = 0;
        for (int s = 0; s < SS; ++s) grid_bar(&target);
    } else if (np <= 2)  rec_loop<2 >(hsm, gsm, np, e, u0);
    else if (np <= 4)    rec_loop<4 >(hsm, gsm, np, e, u0);
    else if (np <= 8)    rec_loop<8 >(hsm, gsm, np, e, u0);
    else                 rec_loop<16>(hsm, gsm, np, e, u0);
}

// ============================================================
// Kernel 5: y[b,s,:] = (hsw[2b,s,:] + hsw[2b+1,s,:]) @ Wf^T + bf
//           M=6400, N=256, K=512; 64x64x16 tiles, 4x4 per thread
// ============================================================
__global__ void __launch_bounds__(256) out_kernel(
    const float* __restrict__ Wf, const float* __restrict__ bf,
    float* __restrict__ out)
{
    __shared__ float As[16][68];
    __shared__ float Bs[16][68];
    const int mt = blockIdx.x, nt = blockIdx.y;
    const int tid = threadIdx.x;
    const int tx = tid & 15, ty = tid >> 4;
    const int lr = tid >> 2, lc = (tid & 3) * 4;

    const int m = mt*64 + lr;
    const int b = m / SS, s = m % SS;
    const float* h0 = d_hsw + ((size_t)(2*b  )*SS + s)*HH;
    const float* h1 = d_hsw + ((size_t)(2*b+1)*SS + s)*HH;
    const float* wrow = Wf + (size_t)(nt*64 + lr)*HH;

    float acc[4][4];
    #pragma unroll
    for (int i = 0; i < 4; ++i)
        #pragma unroll
        for (int j = 0; j < 4; ++j) acc[i][j] = 0.f;

    for (int k0 = 0; k0 < HH; k0 += 16) {
        float4 a0 = *(const float4*)(h0 + k0 + lc);
        float4 a1 = *(const float4*)(h1 + k0 + lc);
        float4 bv = *(const float4*)(wrow + k0 + lc);
        __syncthreads();
        As[lc+0][lr]=a0.x+a1.x; As[lc+1][lr]=a0.y+a1.y;
        As[lc+2][lr]=a0.z+a1.z; As[lc+3][lr]=a0.w+a1.w;
        Bs[lc+0][lr]=bv.x; Bs[lc+1][lr]=bv.y; Bs[lc+2][lr]=bv.z; Bs[lc+3][lr]=bv.w;
        __syncthreads();
        #pragma unroll
        for (int kk = 0; kk < 16; ++kk) {
            float4 ra = *(const float4*)&As[kk][ty*4];
            float4 rb = *(const float4*)&Bs[kk][tx*4];
            float fa[4] = {ra.x,ra.y,ra.z,ra.w};
            float fb[4] = {rb.x,rb.y,rb.z,rb.w};
            #pragma unroll
            for (int i = 0; i < 4; ++i)
                #pragma unroll
                for (int j = 0; j < 4; ++j)
                    acc[i][j] = fmaf(fa[i], fb[j], acc[i][j]);
        }
    }

    #pragma unroll
    for (int i = 0; i < 4; ++i) {
        int mm = mt*64 + ty*4 + i;
        #pragma unroll
        for (int j = 0; j < 4; ++j) {
            int o = nt*64 + tx*4 + j;
            out[(size_t)mm*OUTD + o] = acc[i][j] + bf[o];
        }
    }
}

// ============================================================
extern "C" void kernel_launch(void* const* d_in, const int* in_sizes, int n_in,
                              void* d_out, int out_size)
{
    const float* x    = (const float*)d_in[0];
    const float* spk  = (const float*)d_in[1];
    const float* Wg   = (const float*)d_in[2];
    const float* bg   = (const float*)d_in[3];
    const float* W_ih = (const float*)d_in[4];
    const float* W_hh = (const float*)d_in[5];
    const float* b_ih = (const float*)d_in[6];
    const float* b_hh = (const float*)d_in[7];
    const float* Wf   = (const float*)d_in[8];
    const float* bf   = (const float*)d_in[9];
    float* out = (float*)d_out;

    gate_kernel<<<1, 256>>>(spk, Wg, bg, out, out_size);
    transpose_kernel<<<dim3(16, 64, 8), dim3(32, 8)>>>(W_hh);
    xp_kernel<<<dim3(16, 4, NPAIR), 256>>>(x, W_ih, b_ih, b_hh);
    rec_kernel<<<NB_REC, 256>>>();
    out_kernel<<<dim3(100, 4), 256>>>(Wf, bf, out);
}

// round 3
// speedup vs baseline: 1.1953x; 1.1953x over previous
#include <cuda_runtime.h>

// Problem constants
#define BB    16
#define SS    400
#define DD    768
#define HH    512
#define OUTD  256
#define SKPD  192
#define EE    8
#define NPAIR 32         // B * K, exactly 2 experts per batch
#define H4    2048       // 4*H
#define YELEMS (BB*SS*OUTD)
#define NB_REC 128       // 8 experts * 16 u-chunks
#define JC    320        // j-rows of W_hh cached in smem per rec block
#define REC_SMEM ((JC*128 + 16*HH + 16*4*32) * 4)   // 204800 B

// ---------------- device scratch (static, no allocs) ----------------
__device__ float d_WT[EE*HH*H4];             // W_hh transposed: [e][j][k]
__device__ float d_xp[NPAIR*SS*H4];          // input projections per pair
__device__ float d_hsw[NPAIR*SS*HH];         // gate-weighted h sequence
__device__ float d_hbuf[2*NPAIR*HH];         // double-buffered h state
__device__ int   d_pair_e[NPAIR];
__device__ float d_pair_g[NPAIR];
__device__ int   d_epairs[EE*16];            // pair indices per expert
__device__ int   d_ecnt[EE];
__device__ unsigned d_ebar[EE];              // per-expert barriers

// ============================================================
// Kernel 1: gating + loss + bookkeeping + state init
// ============================================================
__global__ void __launch_bounds__(256) gate_kernel(
    const float* __restrict__ spk, const float* __restrict__ Wg,
    const float* __restrict__ bg, float* __restrict__ out, int out_size)
{
    __shared__ float lg[BB][EE];
    __shared__ float gm[BB][EE];
    int tid = threadIdx.x;

    if (tid < BB*EE) {
        int b = tid >> 3, e = tid & 7;
        float s = bg[e];
        for (int k = 0; k < SKPD; ++k) s += spk[b*SKPD + k] * Wg[e*SKPD + k];
        lg[b][e] = s;
        gm[b][e] = 0.f;
    }
    __syncthreads();

    if (tid < BB) {
        int b = tid;
        int i0 = 0; float m0 = lg[b][0];
        for (int e = 1; e < EE; ++e) if (lg[b][e] > m0) { m0 = lg[b][e]; i0 = e; }
        int i1 = -1; float m1 = -1e30f;
        for (int e = 0; e < EE; ++e) if (e != i0 && lg[b][e] > m1) { m1 = lg[b][e]; i1 = e; }
        float e1v = __expf(m1 - m0);
        float den = 1.f + e1v;
        float g0 = 1.f / den, g1 = e1v / den;
        d_pair_e[2*b]   = i0;  d_pair_e[2*b+1] = i1;
        d_pair_g[2*b]   = g0;  d_pair_g[2*b+1] = g1;
        gm[b][i0] = g0; gm[b][i1] = g1;
    }
    __syncthreads();

    if (tid == 0) {
        int cnt[EE];
        for (int e = 0; e < EE; ++e) cnt[e] = 0;
        for (int p = 0; p < NPAIR; ++p) {
            int e = d_pair_e[p];
            d_epairs[e*16 + cnt[e]] = p;
            cnt[e]++;
        }
        for (int e = 0; e < EE; ++e) { d_ecnt[e] = cnt[e]; d_ebar[e] = 0u; }

        float imp[EE], ldv[EE];
        for (int e = 0; e < EE; ++e) { imp[e] = 0.f; ldv[e] = (float)cnt[e]; }
        for (int b = 0; b < BB; ++b)
            for (int e = 0; e < EE; ++e) imp[e] += gm[b][e];

        float loss = 0.f;
        for (int which = 0; which < 2; ++which) {
            const float* v = which ? ldv : imp;
            float mean = 0.f;
            for (int e = 0; e < EE; ++e) mean += v[e];
            mean /= (float)EE;
            float var = 0.f;
            for (int e = 0; e < EE; ++e) { float d = v[e]-mean; var += d*d; }
            var /= (float)(EE - 1);
            loss += var / (mean*mean + 1e-10f);
        }
        loss *= 0.01f;
        for (int i = YELEMS; i < out_size; ++i) out[i] = loss;
    }

    for (int i = tid; i < 2*NPAIR*HH; i += blockDim.x) d_hbuf[i] = 0.f;
}

// ============================================================
// Kernel 2: transpose W_hh -> WT[e][j][k]
// ============================================================
__global__ void transpose_kernel(const float* __restrict__ W_hh)
{
    __shared__ float t[32][33];
    int e  = blockIdx.z;
    int kt = blockIdx.y;
    int jt = blockIdx.x;
    int x = threadIdx.x, y = threadIdx.y;
    const float* src = W_hh + (size_t)e*H4*HH;
    float* dst = d_WT + (size_t)e*HH*H4;
    #pragma unroll
    for (int i = 0; i < 32; i += 8)
        t[y+i][x] = src[(size_t)(kt*32 + y+i)*HH + jt*32 + x];
    __syncthreads();
    #pragma unroll
    for (int i = 0; i < 32; i += 8)
        dst[(size_t)(jt*32 + y+i)*H4 + kt*32 + x] = t[x][y+i];
}

// ============================================================
// Kernel 3: xp = x[b_p] @ W_ih[e_p]^T + biases, tf32 mma
//           128x128 block tile, K-chunk 16, double buffered
// ============================================================
__device__ __forceinline__ unsigned cvt_tf32(float v) {
    unsigned u;
    asm("cvt.rna.tf32.f32 %0, %1;" : "=r"(u) : "f"(v));
    return u;
}

__device__ __forceinline__ void mma_tf32(float* d, const unsigned* a, const unsigned* b) {
    asm volatile(
      "mma.sync.aligned.m16n8k8.row.col.f32.tf32.tf32.f32 "
      "{%0,%1,%2,%3}, {%4,%5,%6,%7}, {%8,%9}, {%0,%1,%2,%3};\n"
      : "+f"(d[0]), "+f"(d[1]), "+f"(d[2]), "+f"(d[3])
      : "r"(a[0]), "r"(a[1]), "r"(a[2]), "r"(a[3]), "r"(b[0]), "r"(b[1]));
}

#define XS 136   // smem row stride (conflict-free frag gathers: 136 % 32 == 8)

__global__ void __launch_bounds__(256) xp_mma_kernel(
    const float* __restrict__ x, const float* __restrict__ W_ih,
    const float* __restrict__ b_ih, const float* __restrict__ b_hh)
{
    const int p = blockIdx.z;
    const int e = d_pair_e[p];
    const int b = p >> 1;
    const float* A  = x    + (size_t)b*SS*DD;      // [400,768] (guarded)
    const float* Bw = W_ih + (size_t)e*H4*DD;      // [2048,768]
    const int m0 = blockIdx.y * 128, n0 = blockIdx.x * 128;

    __shared__ float As[2][16][XS];
    __shared__ float Bs[2][16][XS];

    const int tid  = threadIdx.x;
    const int warp = tid >> 5, lane = tid & 31;
    const int wm = (warp >> 1) * 32;   // 4 warps in M
    const int wn = (warp & 1) * 64;    // 2 warps in N
    const int lr = tid & 127;          // load row
    const int kg = (tid >> 7) * 8;     // load k-group (0 or 8)

    float acc[2][8][4];
    #pragma unroll
    for (int mt = 0; mt < 2; ++mt)
        #pragma unroll
        for (int nt = 0; nt < 8; ++nt)
            #pragma unroll
            for (int c = 0; c < 4; ++c) acc[mt][nt][c] = 0.f;

    const int gm = m0 + lr;
    const float* Aro = A  + (size_t)gm*DD + kg;
    const float* Bro = Bw + (size_t)(n0 + lr)*DD + kg;

    float4 av0, av1, bv0, bv1;
    // prologue: chunk 0
    {
        av0 = av1 = make_float4(0.f,0.f,0.f,0.f);
        if (gm < SS) { av0 = *(const float4*)(Aro); av1 = *(const float4*)(Aro + 4); }
        bv0 = *(const float4*)(Bro); bv1 = *(const float4*)(Bro + 4);
        float a[8] = {av0.x,av0.y,av0.z,av0.w,av1.x,av1.y,av1.z,av1.w};
        float bb[8] = {bv0.x,bv0.y,bv0.z,bv0.w,bv1.x,bv1.y,bv1.z,bv1.w};
        #pragma unroll
        for (int j = 0; j < 8; ++j) {
            As[0][kg+j][lr] = __uint_as_float(cvt_tf32(a[j]));
            Bs[0][kg+j][lr] = __uint_as_float(cvt_tf32(bb[j]));
        }
    }
    __syncthreads();

    const int NC = DD / 16;   // 48 chunks
    for (int c = 0; c < NC; ++c) {
        const int nb = c & 1;
        if (c + 1 < NC) {
            const float* Ap = Aro + (size_t)(c+1)*16;
            const float* Bp = Bro + (size_t)(c+1)*16;
            av0 = av1 = make_float4(0.f,0.f,0.f,0.f);
            if (gm < SS) { av0 = *(const float4*)(Ap); av1 = *(const float4*)(Ap + 4); }
            bv0 = *(const float4*)(Bp); bv1 = *(const float4*)(Bp + 4);
        }

        #pragma unroll
        for (int ks = 0; ks < 16; ks += 8) {
            unsigned afr[2][4];
            #pragma unroll
            for (int mt = 0; mt < 2; ++mt) {
                int mr = wm + mt*16 + (lane >> 2);
                afr[mt][0] = __float_as_uint(As[nb][ks + (lane&3)    ][mr]);
                afr[mt][1] = __float_as_uint(As[nb][ks + (lane&3)    ][mr+8]);
                afr[mt][2] = __float_as_uint(As[nb][ks + (lane&3) + 4][mr]);
                afr[mt][3] = __float_as_uint(As[nb][ks + (lane&3) + 4][mr+8]);
            }
            #pragma unroll
            for (int nt = 0; nt < 8; ++nt) {
                unsigned bfr[2];
                int nc = wn + nt*8 + (lane >> 2);
                bfr[0] = __float_as_uint(Bs[nb][ks + (lane&3)    ][nc]);
                bfr[1] = __float_as_uint(Bs[nb][ks + (lane&3) + 4][nc]);
                mma_tf32(acc[0][nt], afr[0], bfr);
                mma_tf32(acc[1][nt], afr[1], bfr);
            }
        }

        if (c + 1 < NC) {
            float a[8] = {av0.x,av0.y,av0.z,av0.w,av1.x,av1.y,av1.z,av1.w};
            float bb[8] = {bv0.x,bv0.y,bv0.z,bv0.w,bv1.x,bv1.y,bv1.z,bv1.w};
            #pragma unroll
            for (int j = 0; j < 8; ++j) {
                As[nb^1][kg+j][lr] = __uint_as_float(cvt_tf32(a[j]));
                Bs[nb^1][kg+j][lr] = __uint_as_float(cvt_tf32(bb[j]));
            }
        }
        __syncthreads();
    }

    // epilogue: add biases, store fp32 to d_xp
    #pragma unroll
    for (int nt = 0; nt < 8; ++nt) {
        int gk = n0 + wn + nt*8 + 2*(lane & 3);
        float bias0 = __ldg(b_ih + e*H4 + gk)     + __ldg(b_hh + e*H4 + gk);
        float bias1 = __ldg(b_ih + e*H4 + gk + 1) + __ldg(b_hh + e*H4 + gk + 1);
        #pragma unroll
        for (int mt = 0; mt < 2; ++mt) {
            int r0 = m0 + wm + mt*16 + (lane >> 2);
            if (r0 < SS) {
                float2 v = make_float2(acc[mt][nt][0] + bias0, acc[mt][nt][1] + bias1);
                *(float2*)(d_xp + ((size_t)p*SS + r0)*H4 + gk) = v;
            }
            if (r0 + 8 < SS) {
                float2 v = make_float2(acc[mt][nt][2] + bias0, acc[mt][nt][3] + bias1);
                *(float2*)(d_xp + ((size_t)p*SS + r0 + 8)*H4 + gk) = v;
            }
        }
    }
}

// ============================================================
// Kernel 4: persistent LSTM recurrence, per-expert barriers,
//           62.5% of weights cached in smem
// ============================================================
__device__ __forceinline__ void grid_bar_e(int e, unsigned* target)
{
    __threadfence();
    __syncthreads();
    if (threadIdx.x == 0) {
        atomicAdd(&d_ebar[e], 1u);
        *target += 16;
        while (*((volatile unsigned*)&d_ebar[e]) < *target) { }
    }
    __syncthreads();
}

template<int NP>
__device__ void rec_loop(float* Ws, float* hsm, float* gsm, int np, int e, int u0)
{
    const int tid  = threadIdx.x;
    const int w    = tid >> 5, lane = tid & 31;
    const int gate = w >> 1,  half = w & 1;
    const int jb   = half * 256;

    int plist[NP];
    #pragma unroll
    for (int i = 0; i < NP; ++i)
        plist[i] = d_epairs[e*16 + ((i < np) ? i : 0)];

    // global-weight column pointer (rows beyond JC)
    const float* WTg = d_WT + (size_t)e*HH*H4 + gate*HH + u0 + lane + (size_t)jb*H4;
    // smem-weight column pointer
    const float* Wsl = Ws + gate*32 + lane;
    const int jsm = (half == 0) ? 256 : (JC - 256);   // smem rows in this half

    float c0 = 0.f, c1 = 0.f;
    unsigned target = 0;

    for (int s = 0; s < SS; ++s) {
        const float* hbuf = d_hbuf + (s & 1) * NPAIR*HH;
        float*       hnxt = d_hbuf + ((s+1) & 1) * NPAIR*HH;

        for (int idx = tid; idx < NP*HH; idx += 256) {
            int p = idx >> 9, j = idx & (HH-1);
            hsm[idx] = __ldcg(hbuf + plist[p]*HH + j);
        }
        __syncthreads();

        float acc[NP];
        #pragma unroll
        for (int p = 0; p < NP; ++p) acc[p] = 0.f;

        // smem-cached weight rows
        for (int j = 0; j < jsm; j += 4) {
            float w0 = Wsl[(jb + j + 0)*128];
            float w1 = Wsl[(jb + j + 1)*128];
            float w2 = Wsl[(jb + j + 2)*128];
            float w3 = Wsl[(jb + j + 3)*128];
            #pragma unroll
            for (int p = 0; p < NP; ++p) {
                float4 h4 = *(const float4*)&hsm[p*HH + jb + j];
                acc[p] = fmaf(w3, h4.w, fmaf(w2, h4.z,
                         fmaf(w1, h4.y, fmaf(w0, h4.x, acc[p]))));
            }
        }
        // L2-streamed weight rows
        for (int j = jsm; j < 256; j += 4) {
            float w0 = WTg[(size_t)(j + 0)*H4];
            float w1 = WTg[(size_t)(j + 1)*H4];
            float w2 = WTg[(size_t)(j + 2)*H4];
            float w3 = WTg[(size_t)(j + 3)*H4];
            #pragma unroll
            for (int p = 0; p < NP; ++p) {
                float4 h4 = *(const float4*)&hsm[p*HH + jb + j];
                acc[p] = fmaf(w3, h4.w, fmaf(w2, h4.z,
                         fmaf(w1, h4.y, fmaf(w0, h4.x, acc[p]))));
            }
        }

        if (half == 0) {
            #pragma unroll
            for (int p = 0; p < NP; ++p) gsm[(p*4 + gate)*32 + lane] = acc[p];
        }
        __syncthreads();
        if (half == 1) {
            #pragma unroll
            for (int p = 0; p < NP; ++p) gsm[(p*4 + gate)*32 + lane] += acc[p];
        }
        __syncthreads();

        const int na = np * 32;
        #pragma unroll
        for (int rep = 0; rep < 2; ++rep) {
            int idx = tid + rep*256;
            if (idx < na) {
                int p = idx >> 5, u = idx & 31;
                int pr = plist[p];
                const float* xprow = d_xp + ((size_t)pr*SS + s)*H4 + u0 + u;
                float gi = gsm[(p*4+0)*32+u] + xprow[0];
                float gf = gsm[(p*4+1)*32+u] + xprow[512];
                float gg = gsm[(p*4+2)*32+u] + xprow[1024];
                float go = gsm[(p*4+3)*32+u] + xprow[1536];
                float iv = 1.f / (1.f + __expf(-gi));
                float fv = 1.f / (1.f + __expf(-gf));
                float cp = rep ? c1 : c0;
                float cn = fv * cp + iv * tanhf(gg);
                float hv = (1.f / (1.f + __expf(-go))) * tanhf(cn);
                if (rep) c1 = cn; else c0 = cn;
                hnxt[pr*HH + u0 + u] = hv;
                d_hsw[((size_t)pr*SS + s)*HH + u0 + u] = d_pair_g[pr] * hv;
            }
        }

        grid_bar_e(e, &target);
    }
}

__global__ void __launch_bounds__(256) rec_kernel()
{
    extern __shared__ float rsm[];
    float* Ws  = rsm;                       // [JC][128]
    float* hsm = rsm + JC*128;              // [16][512]
    float* gsm = hsm + 16*HH;               // [16][4][32]

    const int e  = blockIdx.x >> 4;
    const int uc = blockIdx.x & 15;
    const int u0 = uc * 32;
    const int np = d_ecnt[e];
    if (np == 0) return;                    // per-expert barriers: safe to exit

    // preload weight cache: Ws[j][g*32+u] = WT[e][j][g*512 + u0 + u]
    const float* WTb = d_WT + (size_t)e*HH*H4;
    for (int idx = threadIdx.x; idx < JC*128; idx += 256) {
        int j = idx >> 7, col = idx & 127;
        int g = col >> 5, u = col & 31;
        Ws[idx] = WTb[(size_t)j*H4 + g*HH + u0 + u];
    }
    __syncthreads();

    if      (np <= 2)  rec_loop<2 >(Ws, hsm, gsm, np, e, u0);
    else if (np <= 4)  rec_loop<4 >(Ws, hsm, gsm, np, e, u0);
    else if (np <= 8)  rec_loop<8 >(Ws, hsm, gsm, np, e, u0);
    else               rec_loop<16>(Ws, hsm, gsm, np, e, u0);
}

// ============================================================
// Kernel 5: y = (hsw[2b] + hsw[2b+1]) @ Wf^T + bf
// ============================================================
__global__ void __launch_bounds__(256) out_kernel(
    const float* __restrict__ Wf, const float* __restrict__ bf,
    float* __restrict__ out)
{
    __shared__ float As2[16][68];
    __shared__ float Bs2[16][68];
    const int mt = blockIdx.x, nt = blockIdx.y;
    const int tid = threadIdx.x;
    const int tx = tid & 15, ty = tid >> 4;
    const int lr = tid >> 2, lc = (tid & 3) * 4;

    const int m = mt*64 + lr;
    const int b = m / SS, s = m % SS;
    const float* h0 = d_hsw + ((size_t)(2*b  )*SS + s)*HH;
    const float* h1 = d_hsw + ((size_t)(2*b+1)*SS + s)*HH;
    const float* wrow = Wf + (size_t)(nt*64 + lr)*HH;

    float acc[4][4];
    #pragma unroll
    for (int i = 0; i < 4; ++i)
        #pragma unroll
        for (int j = 0; j < 4; ++j) acc[i][j] = 0.f;

    for (int k0 = 0; k0 < HH; k0 += 16) {
        float4 a0 = *(const float4*)(h0 + k0 + lc);
        float4 a1 = *(const float4*)(h1 + k0 + lc);
        float4 bv = *(const float4*)(wrow + k0 + lc);
        __syncthreads();
        As2[lc+0][lr]=a0.x+a1.x; As2[lc+1][lr]=a0.y+a1.y;
        As2[lc+2][lr]=a0.z+a1.z; As2[lc+3][lr]=a0.w+a1.w;
        Bs2[lc+0][lr]=bv.x; Bs2[lc+1][lr]=bv.y; Bs2[lc+2][lr]=bv.z; Bs2[lc+3][lr]=bv.w;
        __syncthreads();
        #pragma unroll
        for (int kk = 0; kk < 16; ++kk) {
            float4 ra = *(const float4*)&As2[kk][ty*4];
            float4 rb = *(const float4*)&Bs2[kk][tx*4];
            float fa[4] = {ra.x,ra.y,ra.z,ra.w};
            float fb[4] = {rb.x,rb.y,rb.z,rb.w};
            #pragma unroll
            for (int i = 0; i < 4; ++i)
                #pragma unroll
                for (int j = 0; j < 4; ++j)
                    acc[i][j] = fmaf(fa[i], fb[j], acc[i][j]);
        }
    }

    #pragma unroll
    for (int i = 0; i < 4; ++i) {
        int mm = mt*64 + ty*4 + i;
        #pragma unroll
        for (int j = 0; j < 4; ++j) {
            int o = nt*64 + tx*4 + j;
            out[(size_t)mm*OUTD + o] = acc[i][j] + bf[o];
        }
    }
}

// ============================================================
extern "C" void kernel_launch(void* const* d_in, const int* in_sizes, int n_in,
                              void* d_out, int out_size)
{
    const float* x    = (const float*)d_in[0];
    const float* spk  = (const float*)d_in[1];
    const float* Wg   = (const float*)d_in[2];
    const float* bg   = (const float*)d_in[3];
    const float* W_ih = (const float*)d_in[4];
    const float* W_hh = (const float*)d_in[5];
    const float* b_ih = (const float*)d_in[6];
    const float* b_hh = (const float*)d_in[7];
    const float* Wf   = (const float*)d_in[8];
    const float* bf   = (const float*)d_in[9];
    float* out = (float*)d_out;

    // idempotent, capture-safe (not stream-ordered, no alloc/sync)
    cudaFuncSetAttribute(rec_kernel,
                         cudaFuncAttributeMaxDynamicSharedMemorySize, REC_SMEM);

    gate_kernel<<<1, 256>>>(spk, Wg, bg, out, out_size);
    transpose_kernel<<<dim3(16, 64, 8), dim3(32, 8)>>>(W_hh);
    xp_mma_kernel<<<dim3(16, 4, NPAIR), 256>>>(x, W_ih, b_ih, b_hh);
    rec_kernel<<<NB_REC, 256, REC_SMEM>>>();
    out_kernel<<<dim3(100, 4), 256>>>(Wf, bf, out);
}